// round 1
// baseline (speedup 1.0000x reference)
#include <cuda_runtime.h>
#include <math.h>

#define BATCH 4096
#define POSED 13
#define HID 256
#define CTXD 256
#define IN_DIM 269     // POSED + CTXD
#define G3 768         // 3*HID

// ------------------------- scratch (device globals; no allocs) ---------------
__device__ float d_cproj[BATCH * HID];
__device__ float d_x[BATCH * HID];
__device__ float d_gi[BATCH * G3];
__device__ float d_gh[BATCH * G3];
__device__ float d_h[BATCH * HID];
__device__ float d_pose[BATCH * POSED];

// ------------------------- init: h=0, pose=last_pose -------------------------
__global__ void init_kernel(const float* __restrict__ last_pose) {
    int i = blockIdx.x * blockDim.x + threadIdx.x;
    if (i < BATCH * HID) d_h[i] = 0.f;
    if (i < BATCH * POSED) d_pose[i] = last_pose[i];
}

// ------------------------- tiled fp32 GEMM: C = A @ W^T + bias ---------------
// A: (M,K) row-major ld=lda.  W: (N,K') row-major ld=ldw, use cols [woff, woff+K)
// C: (M,N) row-major.  Tiles exact: M%128==0, N%128==0, K%16==0.
#define BM 128
#define BN 128
#define BKK 16
#define TM 8
#define TN 8

template <bool VEC>
__global__ __launch_bounds__(256) void gemm_bias(
    const float* __restrict__ A, int lda,
    const float* __restrict__ W, int ldw, int woff,
    const float* __restrict__ bias,
    float* __restrict__ C, int N, int K)
{
    __shared__ float As[BKK][BM + 4];
    __shared__ float Ws[BKK][BN + 4];

    const int tid = threadIdx.x;
    const int m0 = blockIdx.x * BM;
    const int n0 = blockIdx.y * BN;
    const int ty = tid >> 4;     // 0..15
    const int tx = tid & 15;     // 0..15

    float acc[TM][TN];
#pragma unroll
    for (int i = 0; i < TM; i++)
#pragma unroll
        for (int j = 0; j < TN; j++) acc[i][j] = 0.f;

    for (int k0 = 0; k0 < K; k0 += BKK) {
        if (VEC) {
#pragma unroll
            for (int it = 0; it < 2; it++) {
                int idx = tid + it * 256;            // 0..511
                int row = idx >> 2;                  // 0..127
                int kv  = (idx & 3) << 2;            // 0,4,8,12
                float4 a = *(const float4*)&A[(size_t)(m0 + row) * lda + k0 + kv];
                As[kv + 0][row] = a.x; As[kv + 1][row] = a.y;
                As[kv + 2][row] = a.z; As[kv + 3][row] = a.w;
                float4 w = *(const float4*)&W[(size_t)(n0 + row) * ldw + woff + k0 + kv];
                Ws[kv + 0][row] = w.x; Ws[kv + 1][row] = w.y;
                Ws[kv + 2][row] = w.z; Ws[kv + 3][row] = w.w;
            }
        } else {
#pragma unroll
            for (int it = 0; it < 8; it++) {
                int idx = tid + it * 256;            // 0..2047
                int row = idx >> 4;                  // 0..127
                int k   = idx & 15;
                As[k][row] = A[(size_t)(m0 + row) * lda + k0 + k];
                Ws[k][row] = W[(size_t)(n0 + row) * ldw + woff + k0 + k];
            }
        }
        __syncthreads();

#pragma unroll
        for (int kk = 0; kk < BKK; kk++) {
            float af[TM], wf[TN];
#pragma unroll
            for (int i = 0; i < TM; i++) af[i] = As[kk][ty * TM + i];
#pragma unroll
            for (int j = 0; j < TN; j++) wf[j] = Ws[kk][tx * TN + j];
#pragma unroll
            for (int i = 0; i < TM; i++)
#pragma unroll
                for (int j = 0; j < TN; j++)
                    acc[i][j] += af[i] * wf[j];
        }
        __syncthreads();
    }

#pragma unroll
    for (int i = 0; i < TM; i++) {
        int m = m0 + ty * TM + i;
#pragma unroll
        for (int j = 0; j < TN; j++) {
            int n = n0 + tx * TN + j;
            C[(size_t)m * N + n] = acc[i][j] + bias[n];
        }
    }
}

// ------------------------- x = relu(pose @ Wp^T + c_proj) --------------------
// Wp = W_in[:, :13].  One block per batch row, thread j = hidden unit.
__global__ __launch_bounds__(256) void x_kernel(const float* __restrict__ W_in) {
    int b = blockIdx.x;
    int j = threadIdx.x;
    __shared__ float sp[POSED];
    if (j < POSED) sp[j] = d_pose[b * POSED + j];
    __syncthreads();
    float acc = d_cproj[(size_t)b * HID + j];
    const float* wrow = W_in + (size_t)j * IN_DIM;
#pragma unroll
    for (int k = 0; k < POSED; k++) acc += sp[k] * wrow[k];
    d_x[(size_t)b * HID + j] = fmaxf(acc, 0.f);
}

// ------------------------- GRU gates + h update + pose update ----------------
__global__ __launch_bounds__(256) void gate_kernel(
    const float* __restrict__ W_out, const float* __restrict__ b_out,
    float* __restrict__ out, int t, int T)
{
    int b = blockIdx.x;
    int j = threadIdx.x;   // 0..255

    const float* gi = d_gi + (size_t)b * G3;
    const float* gh = d_gh + (size_t)b * G3;

    float ir = gi[j],        hr = gh[j];
    float iz = gi[HID + j],  hz = gh[HID + j];
    float inn = gi[2 * HID + j], hn = gh[2 * HID + j];

    float r = 1.f / (1.f + expf(-(ir + hr)));
    float z = 1.f / (1.f + expf(-(iz + hz)));
    float n = tanhf(inn + r * hn);

    float hprev = d_h[(size_t)b * HID + j];
    float hnew  = (1.f - z) * n + z * hprev;
    d_h[(size_t)b * HID + j] = hnew;

    // pose delta: 13 dot products of hnew row with W_out rows
    __shared__ float warp_part[POSED][8];
#pragma unroll
    for (int p = 0; p < POSED; p++) {
        float v = hnew * W_out[p * HID + j];
#pragma unroll
        for (int o = 16; o > 0; o >>= 1)
            v += __shfl_down_sync(0xffffffffu, v, o);
        if ((j & 31) == 0) warp_part[p][j >> 5] = v;
    }
    __syncthreads();

    __shared__ float pnew[16];
    if (j < POSED) {
        float s = 0.f;
#pragma unroll
        for (int w = 0; w < 8; w++) s += warp_part[j][w];
        pnew[j] = d_pose[b * POSED + j] + s + b_out[j];
    }
    __syncthreads();

    if (j < POSED) {
        float v = pnew[j];
        if (j >= 3 && j <= 6) {
            float q = sqrtf(pnew[3] * pnew[3] + pnew[4] * pnew[4] +
                            pnew[5] * pnew[5] + pnew[6] * pnew[6]);
            q = fmaxf(q, 1e-12f);
            v /= q;
        }
        d_pose[b * POSED + j] = v;
        out[((size_t)b * T + t) * POSED + j] = v;
    }
}

// ------------------------- launch --------------------------------------------
extern "C" void kernel_launch(void* const* d_in, const int* in_sizes, int n_in,
                              void* d_out, int out_size)
{
    const float* last_pose = (const float*)d_in[0];
    const float* context   = (const float*)d_in[1];
    /* d_in[2] = num_future (int scalar on device) — T derived from out_size */
    const float* W_in  = (const float*)d_in[3];
    const float* b_in  = (const float*)d_in[4];
    const float* W_ih  = (const float*)d_in[5];
    const float* b_ih  = (const float*)d_in[6];
    const float* W_hh  = (const float*)d_in[7];
    const float* b_hh  = (const float*)d_in[8];
    const float* W_out = (const float*)d_in[9];
    const float* b_out = (const float*)d_in[10];
    float* out = (float*)d_out;

    const int T = out_size / (BATCH * POSED);

    float *p_cproj, *p_x, *p_gi, *p_gh, *p_h;
    cudaGetSymbolAddress((void**)&p_cproj, d_cproj);
    cudaGetSymbolAddress((void**)&p_x, d_x);
    cudaGetSymbolAddress((void**)&p_gi, d_gi);
    cudaGetSymbolAddress((void**)&p_gh, d_gh);
    cudaGetSymbolAddress((void**)&p_h, d_h);

    init_kernel<<<(BATCH * HID + 255) / 256, 256>>>(last_pose);

    // c_proj = context @ W_in[:,13:]^T + b_in   (once; misaligned woff -> scalar path)
    gemm_bias<false><<<dim3(BATCH / BM, HID / BN), 256>>>(
        context, CTXD, W_in, IN_DIM, POSED, b_in, p_cproj, HID, CTXD);

    for (int t = 0; t < T; t++) {
        x_kernel<<<BATCH, 256>>>(W_in);

        // gi = x @ W_ih^T + b_ih
        gemm_bias<true><<<dim3(BATCH / BM, G3 / BN), 256>>>(
            p_x, HID, W_ih, HID, 0, b_ih, p_gi, G3, HID);
        // gh = h @ W_hh^T + b_hh
        gemm_bias<true><<<dim3(BATCH / BM, G3 / BN), 256>>>(
            p_h, HID, W_hh, HID, 0, b_hh, p_gh, G3, HID);

        gate_kernel<<<BATCH, 256>>>(W_out, b_out, out, t, T);
    }
}

// round 2
// speedup vs baseline: 1.5567x; 1.5567x over previous
#include <cuda_runtime.h>
#include <math.h>

#define BATCH 4096
#define POSED 13
#define HID 256
#define IN_DIM 269     // POSED + CTX
#define XHLD 512       // [x | h] row stride
#define GCOLS 1024     // [s_r(256) | s_z(256) | i_n(256) | h_n(256)]

// ------------------------- scratch (device globals) --------------------------
__device__ float d_xh[BATCH * XHLD];      // [:,0:256]=x, [:,256:512]=h
__device__ float d_g[BATCH * GCOLS];
__device__ float d_cproj[BATCH * HID];
__device__ float d_pose[BATCH * POSED];
__device__ float d_Wcat[512 * 512];       // rows=r,z gates; cols=[W_ih | W_hh]
__device__ float d_Wctx[256 * 256];       // W_in[:, 13:269] repacked (aligned)
__device__ float d_biasv[GCOLS];

// ------------------------- init: h=0, pose=last_pose -------------------------
__global__ void init_kernel(const float* __restrict__ last_pose) {
    int i = blockIdx.x * blockDim.x + threadIdx.x;
    if (i < BATCH * HID) d_xh[(i >> 8) * XHLD + 256 + (i & 255)] = 0.f;
    if (i < BATCH * POSED) d_pose[i] = last_pose[i];
}

// ------------------------- weight repack + fused bias ------------------------
__global__ void prep_kernel(const float* __restrict__ W_ih, const float* __restrict__ W_hh,
                            const float* __restrict__ b_ih, const float* __restrict__ b_hh,
                            const float* __restrict__ W_in) {
    int i = blockIdx.x * blockDim.x + threadIdx.x;
    if (i < 512 * 512) {
        int n = i >> 9, k = i & 511;
        d_Wcat[i] = (k < 256) ? W_ih[n * 256 + k] : W_hh[n * 256 + (k - 256)];
    }
    if (i < 256 * 256) {
        int n = i >> 8, k = i & 255;
        d_Wctx[i] = W_in[n * IN_DIM + POSED + k];
    }
    if (i < GCOLS) {
        d_biasv[i] = (i < 512) ? (b_ih[i] + b_hh[i])
                   : (i < 768) ? b_ih[i]
                               : b_hh[i - 256];
    }
}

// ------------------------- double-buffered fp32 GEMM core --------------------
// C[m0+.., :128] (+n-offset applied by caller) = A(128xK) @ Wt(128xK)^T + bias
// 128x128 tile, BK=16, 256 threads, 8x8 per thread, reg-prefetch + 2 smem bufs.
__device__ __forceinline__ void gemm_core(
    const float* __restrict__ A, int lda,
    const float* __restrict__ Wt, int ldw, int K,
    const float* __restrict__ biasp,
    float* __restrict__ Cp, int ldc, int m0)
{
    __shared__ float As[2][16][132];
    __shared__ float Ws[2][16][132];

    const int tid = threadIdx.x;
    const int ty = tid >> 4;          // 0..15
    const int tx = tid & 15;          // 0..15
    const int r0 = tid >> 2;          // 0..63
    const int kv = (tid & 3) << 2;    // 0,4,8,12

    float acc[8][8];
#pragma unroll
    for (int i = 0; i < 8; i++)
#pragma unroll
        for (int j = 0; j < 8; j++) acc[i][j] = 0.f;

    const float* Ar0 = A + (size_t)(m0 + r0) * lda + kv;
    const float* Ar1 = A + (size_t)(m0 + 64 + r0) * lda + kv;
    const float* Wr0 = Wt + (size_t)r0 * ldw + kv;
    const float* Wr1 = Wt + (size_t)(64 + r0) * ldw + kv;

    float4 pa0 = *(const float4*)Ar0;
    float4 pa1 = *(const float4*)Ar1;
    float4 pw0 = *(const float4*)Wr0;
    float4 pw1 = *(const float4*)Wr1;

    As[0][kv + 0][r0] = pa0.x; As[0][kv + 1][r0] = pa0.y; As[0][kv + 2][r0] = pa0.z; As[0][kv + 3][r0] = pa0.w;
    As[0][kv + 0][64 + r0] = pa1.x; As[0][kv + 1][64 + r0] = pa1.y; As[0][kv + 2][64 + r0] = pa1.z; As[0][kv + 3][64 + r0] = pa1.w;
    Ws[0][kv + 0][r0] = pw0.x; Ws[0][kv + 1][r0] = pw0.y; Ws[0][kv + 2][r0] = pw0.z; Ws[0][kv + 3][r0] = pw0.w;
    Ws[0][kv + 0][64 + r0] = pw1.x; Ws[0][kv + 1][64 + r0] = pw1.y; Ws[0][kv + 2][64 + r0] = pw1.z; Ws[0][kv + 3][64 + r0] = pw1.w;
    __syncthreads();

    const int nk = K >> 4;
    for (int kt = 0; kt < nk; kt++) {
        const int buf = kt & 1;
        if (kt + 1 < nk) {
            int k0 = (kt + 1) << 4;
            pa0 = *(const float4*)(Ar0 + k0);
            pa1 = *(const float4*)(Ar1 + k0);
            pw0 = *(const float4*)(Wr0 + k0);
            pw1 = *(const float4*)(Wr1 + k0);
        }
#pragma unroll
        for (int kk = 0; kk < 16; kk++) {
            float4 a0 = *(const float4*)&As[buf][kk][ty * 8];
            float4 a1 = *(const float4*)&As[buf][kk][ty * 8 + 4];
            float4 w0 = *(const float4*)&Ws[buf][kk][tx * 8];
            float4 w1 = *(const float4*)&Ws[buf][kk][tx * 8 + 4];
            float af[8] = {a0.x, a0.y, a0.z, a0.w, a1.x, a1.y, a1.z, a1.w};
            float wf[8] = {w0.x, w0.y, w0.z, w0.w, w1.x, w1.y, w1.z, w1.w};
#pragma unroll
            for (int i = 0; i < 8; i++)
#pragma unroll
                for (int j = 0; j < 8; j++)
                    acc[i][j] += af[i] * wf[j];
        }
        if (kt + 1 < nk) {
            const int nb = buf ^ 1;
            As[nb][kv + 0][r0] = pa0.x; As[nb][kv + 1][r0] = pa0.y; As[nb][kv + 2][r0] = pa0.z; As[nb][kv + 3][r0] = pa0.w;
            As[nb][kv + 0][64 + r0] = pa1.x; As[nb][kv + 1][64 + r0] = pa1.y; As[nb][kv + 2][64 + r0] = pa1.z; As[nb][kv + 3][64 + r0] = pa1.w;
            Ws[nb][kv + 0][r0] = pw0.x; Ws[nb][kv + 1][r0] = pw0.y; Ws[nb][kv + 2][r0] = pw0.z; Ws[nb][kv + 3][r0] = pw0.w;
            Ws[nb][kv + 0][64 + r0] = pw1.x; Ws[nb][kv + 1][64 + r0] = pw1.y; Ws[nb][kv + 2][64 + r0] = pw1.z; Ws[nb][kv + 3][64 + r0] = pw1.w;
            __syncthreads();
        }
    }

#pragma unroll
    for (int i = 0; i < 8; i++) {
        float* crow = Cp + (size_t)(m0 + ty * 8 + i) * ldc + tx * 8;
        float4 b0 = *(const float4*)&biasp[tx * 8];
        float4 b1 = *(const float4*)&biasp[tx * 8 + 4];
        float4 o0 = make_float4(acc[i][0] + b0.x, acc[i][1] + b0.y, acc[i][2] + b0.z, acc[i][3] + b0.w);
        float4 o1 = make_float4(acc[i][4] + b1.x, acc[i][5] + b1.y, acc[i][6] + b1.z, acc[i][7] + b1.w);
        *(float4*)crow = o0;
        *(float4*)(crow + 4) = o1;
    }
}

// cproj = context @ W_in[:,13:]^T + b_in   (once)
__global__ __launch_bounds__(256, 2) void cproj_gemm(const float* __restrict__ context,
                                                     const float* __restrict__ b_in) {
    int m0 = blockIdx.x * 128;
    int y = blockIdx.y;                      // 0..1
    gemm_core(context, 256, d_Wctx + y * 128 * 256, 256, 256,
              b_in + y * 128, d_cproj + y * 128, HID, m0);
}

// per-step: g = [ [x|h]@Wcat^T | x@Wih_n^T | h@Whh_n^T ] + biasv
__global__ __launch_bounds__(256, 2) void step_gemm(const float* __restrict__ W_ih,
                                                    const float* __restrict__ W_hh) {
    int m0 = blockIdx.x * 128;
    int y = blockIdx.y;                      // 0..7
    const float* A; const float* Wt; int K, ldw, n0;
    if (y < 4)      { A = d_xh;       Wt = d_Wcat + y * 128 * 512;            ldw = 512; K = 512; n0 = y * 128; }
    else if (y < 6) { A = d_xh;       Wt = W_ih + (512 + (y - 4) * 128) * HID; ldw = HID; K = 256; n0 = 512 + (y - 4) * 128; }
    else            { A = d_xh + 256; Wt = W_hh + (512 + (y - 6) * 128) * HID; ldw = HID; K = 256; n0 = 768 + (y - 6) * 128; }
    gemm_core(A, XHLD, Wt, ldw, K, d_biasv + n0, d_g + n0, GCOLS, m0);
}

// ------------------------- initial x = relu(pose@Wp^T + cproj) ---------------
__global__ __launch_bounds__(256) void x_init(const float* __restrict__ W_in) {
    int b = blockIdx.x, j = threadIdx.x;
    __shared__ float sp[16];
    if (j < POSED) sp[j] = d_pose[b * POSED + j];
    __syncthreads();
    float acc = d_cproj[(size_t)b * HID + j];
#pragma unroll
    for (int k = 0; k < POSED; k++) acc += sp[k] * W_in[(size_t)j * IN_DIM + k];
    d_xh[(size_t)b * XHLD + j] = fmaxf(acc, 0.f);
}

// ------------------------- gates + h + pose + quat + next-x ------------------
__global__ __launch_bounds__(256) void gate_kernel(
    const float* __restrict__ W_out, const float* __restrict__ b_out,
    const float* __restrict__ W_in,
    float* __restrict__ out, int t, int T)
{
    int b = blockIdx.x, j = threadIdx.x;
    const float* g = d_g + (size_t)b * GCOLS;

    float sr = g[j], sz = g[256 + j], in_ = g[512 + j], hn = g[768 + j];
    float r = 1.f / (1.f + expf(-sr));
    float z = 1.f / (1.f + expf(-sz));
    float n = tanhf(in_ + r * hn);

    float hprev = d_xh[(size_t)b * XHLD + 256 + j];
    float hnew = (1.f - z) * n + z * hprev;
    d_xh[(size_t)b * XHLD + 256 + j] = hnew;

    __shared__ float warp_part[POSED][8];
#pragma unroll
    for (int p = 0; p < POSED; p++) {
        float v = hnew * W_out[p * HID + j];
#pragma unroll
        for (int o = 16; o > 0; o >>= 1)
            v += __shfl_down_sync(0xffffffffu, v, o);
        if ((j & 31) == 0) warp_part[p][j >> 5] = v;
    }
    __syncthreads();

    __shared__ float pnew[16];
    if (j < POSED) {
        float s = 0.f;
#pragma unroll
        for (int w = 0; w < 8; w++) s += warp_part[j][w];
        pnew[j] = d_pose[b * POSED + j] + s + b_out[j];
    }
    __syncthreads();

    __shared__ float spf[16];
    if (j < POSED) {
        float v = pnew[j];
        if (j >= 3 && j <= 6) {
            float q = sqrtf(pnew[3] * pnew[3] + pnew[4] * pnew[4] +
                            pnew[5] * pnew[5] + pnew[6] * pnew[6]);
            v /= fmaxf(q, 1e-12f);
        }
        spf[j] = v;
        d_pose[b * POSED + j] = v;
        out[((size_t)b * T + t) * POSED + j] = v;
    }
    __syncthreads();

    // next x = relu(pose_new @ Wp^T + cproj)
    float acc = d_cproj[(size_t)b * HID + j];
#pragma unroll
    for (int k = 0; k < POSED; k++) acc += spf[k] * W_in[(size_t)j * IN_DIM + k];
    d_xh[(size_t)b * XHLD + j] = fmaxf(acc, 0.f);
}

// ------------------------- launch --------------------------------------------
extern "C" void kernel_launch(void* const* d_in, const int* in_sizes, int n_in,
                              void* d_out, int out_size)
{
    const float* last_pose = (const float*)d_in[0];
    const float* context   = (const float*)d_in[1];
    const float* W_in  = (const float*)d_in[3];
    const float* b_in  = (const float*)d_in[4];
    const float* W_ih  = (const float*)d_in[5];
    const float* b_ih  = (const float*)d_in[6];
    const float* W_hh  = (const float*)d_in[7];
    const float* b_hh  = (const float*)d_in[8];
    const float* W_out = (const float*)d_in[9];
    const float* b_out = (const float*)d_in[10];
    float* out = (float*)d_out;

    const int T = out_size / (BATCH * POSED);

    init_kernel<<<(BATCH * HID + 255) / 256, 256>>>(last_pose);
    prep_kernel<<<(512 * 512 + 255) / 256, 256>>>(W_ih, W_hh, b_ih, b_hh, W_in);
    cproj_gemm<<<dim3(BATCH / 128, 2), 256>>>(context, b_in);
    x_init<<<BATCH, 256>>>(W_in);

    for (int t = 0; t < T; t++) {
        step_gemm<<<dim3(BATCH / 128, 8), 256>>>(W_ih, W_hh);
        gate_kernel<<<BATCH, 256>>>(W_out, b_out, W_in, out, t, T);
    }
}

// round 4
// speedup vs baseline: 2.3255x; 1.4938x over previous
#include <cuda_runtime.h>
#include <cuda_bf16.h>
#include <math.h>
#include <stdint.h>

#define BATCH 4096
#define POSED 13
#define HID 256
#define IN_DIM 269
#define AK 1536          // A' row length: [ah(512) | al(512) | ah(512)]
#define GCOLS 1024       // [s_r | s_z | i_n | h_n]

// ------------------------- scratch (device globals) --------------------------
__device__ __align__(16) __nv_bfloat16 d_A[BATCH * AK];
__device__ __align__(16) float d_h[BATCH * HID];
__device__ __align__(16) float d_g[BATCH * GCOLS];
__device__ __align__(16) float d_cproj[BATCH * HID];
__device__ float d_pose[BATCH * POSED];
__device__ __align__(16) __nv_bfloat16 d_Wcat_b[512 * 1536];   // rz gates, [bh|bh|bl]
__device__ __align__(16) __nv_bfloat16 d_Wihn_b[256 * 768];    // i_n
__device__ __align__(16) __nv_bfloat16 d_Whhn_b[256 * 768];    // h_n
__device__ __align__(16) float d_Wctx[256 * 256];
__device__ float d_biasv[GCOLS];

// ------------------------- helpers -------------------------------------------
__device__ __forceinline__ uint32_t smem_u32(const void* p) {
    uint32_t a;
    asm("{ .reg .u64 t; cvta.to.shared.u64 t, %1; cvt.u32.u64 %0, t; }" : "=r"(a) : "l"(p));
    return a;
}
__device__ __forceinline__ void cp16(uint32_t dst, const void* src) {
    asm volatile("cp.async.cg.shared.global [%0], [%1], 16;" :: "r"(dst), "l"(src) : "memory");
}
#define CP_COMMIT() asm volatile("cp.async.commit_group;" ::: "memory")
#define CP_WAIT1()  asm volatile("cp.async.wait_group 1;" ::: "memory")

__device__ __forceinline__ void bf16_split(float v, __nv_bfloat16& hi, __nv_bfloat16& lo) {
    hi = __float2bfloat16_rn(v);
    lo = __float2bfloat16_rn(v - __bfloat162float(hi));
}

// ------------------------- init ----------------------------------------------
__global__ void init_kernel(const float* __restrict__ last_pose) {
    int i = blockIdx.x * blockDim.x + threadIdx.x;
    if (i < BATCH * HID) {
        d_h[i] = 0.f;
        int b = i >> 8, j = i & 255;
        __nv_bfloat16 z = __float2bfloat16_rn(0.f);
        size_t base = (size_t)b * AK;
        d_A[base + 256 + j] = z;     // h_hi
        d_A[base + 768 + j] = z;     // h_lo
        d_A[base + 1280 + j] = z;    // h_hi (repeat)
    }
    if (i < BATCH * POSED) d_pose[i] = last_pose[i];
}

// ------------------------- weight repack: bf16 splits + fused bias -----------
__global__ void prep_kernel(const float* __restrict__ W_ih, const float* __restrict__ W_hh,
                            const float* __restrict__ b_ih, const float* __restrict__ b_hh,
                            const float* __restrict__ W_in) {
    int i = blockIdx.x * blockDim.x + threadIdx.x;
    // Wcat_b: 512 x 1536
    if (i < 512 * 1536) {
        int n = i / 1536, col = i % 1536;
        int seg = col >> 9, k = col & 511;
        float w = (k < 256) ? W_ih[n * 256 + k] : W_hh[n * 256 + (k - 256)];
        __nv_bfloat16 hi, lo; bf16_split(w, hi, lo);
        d_Wcat_b[i] = (seg < 2) ? hi : lo;
    }
    // Wihn_b / Whhn_b: 256 x 768 each
    if (i < 256 * 768) {
        int n = i / 768, col = i % 768;
        int seg = col >> 8, k = col & 255;
        {
            float w = W_ih[(512 + n) * 256 + k];
            __nv_bfloat16 hi, lo; bf16_split(w, hi, lo);
            d_Wihn_b[i] = (seg < 2) ? hi : lo;
        }
        {
            float w = W_hh[(512 + n) * 256 + k];
            __nv_bfloat16 hi, lo; bf16_split(w, hi, lo);
            d_Whhn_b[i] = (seg < 2) ? hi : lo;
        }
    }
    if (i < 256 * 256) {
        int n = i >> 8, k = i & 255;
        d_Wctx[i] = W_in[n * IN_DIM + POSED + k];
    }
    if (i < GCOLS) {
        d_biasv[i] = (i < 512) ? (b_ih[i] + b_hh[i])
                   : (i < 768) ? b_ih[i]
                               : b_hh[i - 256];
    }
}

// ------------------------- fp32 GEMM (one-time cproj) ------------------------
__global__ __launch_bounds__(256, 2) void cproj_gemm(const float* __restrict__ context,
                                                     const float* __restrict__ b_in) {
    __shared__ float As[2][16][132];
    __shared__ float Ws[2][16][132];
    const int tid = threadIdx.x;
    const int ty = tid >> 4, tx = tid & 15;
    const int r0 = tid >> 2, kv = (tid & 3) << 2;
    const int m0 = blockIdx.x * 128;
    const int y = blockIdx.y;
    const float* A = context;
    const float* Wt = d_Wctx + y * 128 * 256;
    const float* biasp = b_in + y * 128;
    float* Cp = d_cproj + y * 128;

    float acc[8][8];
#pragma unroll
    for (int i = 0; i < 8; i++)
#pragma unroll
        for (int j = 0; j < 8; j++) acc[i][j] = 0.f;

    const float* Ar0 = A + (size_t)(m0 + r0) * 256 + kv;
    const float* Ar1 = A + (size_t)(m0 + 64 + r0) * 256 + kv;
    const float* Wr0 = Wt + (size_t)r0 * 256 + kv;
    const float* Wr1 = Wt + (size_t)(64 + r0) * 256 + kv;

    float4 pa0 = *(const float4*)Ar0, pa1 = *(const float4*)Ar1;
    float4 pw0 = *(const float4*)Wr0, pw1 = *(const float4*)Wr1;
    As[0][kv+0][r0]=pa0.x; As[0][kv+1][r0]=pa0.y; As[0][kv+2][r0]=pa0.z; As[0][kv+3][r0]=pa0.w;
    As[0][kv+0][64+r0]=pa1.x; As[0][kv+1][64+r0]=pa1.y; As[0][kv+2][64+r0]=pa1.z; As[0][kv+3][64+r0]=pa1.w;
    Ws[0][kv+0][r0]=pw0.x; Ws[0][kv+1][r0]=pw0.y; Ws[0][kv+2][r0]=pw0.z; Ws[0][kv+3][r0]=pw0.w;
    Ws[0][kv+0][64+r0]=pw1.x; Ws[0][kv+1][64+r0]=pw1.y; Ws[0][kv+2][64+r0]=pw1.z; Ws[0][kv+3][64+r0]=pw1.w;
    __syncthreads();

    for (int kt = 0; kt < 16; kt++) {
        const int buf = kt & 1;
        if (kt + 1 < 16) {
            int k0 = (kt + 1) << 4;
            pa0 = *(const float4*)(Ar0 + k0); pa1 = *(const float4*)(Ar1 + k0);
            pw0 = *(const float4*)(Wr0 + k0); pw1 = *(const float4*)(Wr1 + k0);
        }
#pragma unroll
        for (int kk = 0; kk < 16; kk++) {
            float4 a0 = *(const float4*)&As[buf][kk][ty*8];
            float4 a1 = *(const float4*)&As[buf][kk][ty*8+4];
            float4 w0 = *(const float4*)&Ws[buf][kk][tx*8];
            float4 w1 = *(const float4*)&Ws[buf][kk][tx*8+4];
            float af[8]={a0.x,a0.y,a0.z,a0.w,a1.x,a1.y,a1.z,a1.w};
            float wf[8]={w0.x,w0.y,w0.z,w0.w,w1.x,w1.y,w1.z,w1.w};
#pragma unroll
            for (int i = 0; i < 8; i++)
#pragma unroll
                for (int j = 0; j < 8; j++) acc[i][j] += af[i] * wf[j];
        }
        if (kt + 1 < 16) {
            const int nb = buf ^ 1;
            As[nb][kv+0][r0]=pa0.x; As[nb][kv+1][r0]=pa0.y; As[nb][kv+2][r0]=pa0.z; As[nb][kv+3][r0]=pa0.w;
            As[nb][kv+0][64+r0]=pa1.x; As[nb][kv+1][64+r0]=pa1.y; As[nb][kv+2][64+r0]=pa1.z; As[nb][kv+3][64+r0]=pa1.w;
            Ws[nb][kv+0][r0]=pw0.x; Ws[nb][kv+1][r0]=pw0.y; Ws[nb][kv+2][r0]=pw0.z; Ws[nb][kv+3][r0]=pw0.w;
            Ws[nb][kv+0][64+r0]=pw1.x; Ws[nb][kv+1][64+r0]=pw1.y; Ws[nb][kv+2][64+r0]=pw1.z; Ws[nb][kv+3][64+r0]=pw1.w;
            __syncthreads();
        }
    }
#pragma unroll
    for (int i = 0; i < 8; i++) {
        float* crow = Cp + (size_t)(m0 + ty*8 + i) * HID + tx*8;
        float4 b0 = *(const float4*)&biasp[tx*8];
        float4 b1 = *(const float4*)&biasp[tx*8+4];
        *(float4*)crow = make_float4(acc[i][0]+b0.x, acc[i][1]+b0.y, acc[i][2]+b0.z, acc[i][3]+b0.w);
        *(float4*)(crow+4) = make_float4(acc[i][4]+b1.x, acc[i][5]+b1.y, acc[i][6]+b1.z, acc[i][7]+b1.w);
    }
}

// ------------------------- bf16 mma.sync step GEMM ---------------------------
// 128x128 block tile, 8 warps (2Mx4N), warp tile 64x32, k-chunk 32, 2 stages.
#define ASTRIDE 40   // bf16 elems per smem row (32 data + 8 pad); 80B = 5*16B

__global__ __launch_bounds__(256, 2) void step_gemm_mma() {
    __shared__ __align__(16) __nv_bfloat16 sA[2][128][ASTRIDE];
    __shared__ __align__(16) __nv_bfloat16 sB[2][128][ASTRIDE];

    const int tid = threadIdx.x;
    const int wid = tid >> 5;
    const int lane = tid & 31;
    const int wm = (wid >> 2) * 64;    // warp M offset (0 or 64)
    const int wn = (wid & 3) * 32;     // warp N offset
    const int m0 = blockIdx.x * 128;
    const int y = blockIdx.y;          // 0..7

    // dispatch
    const __nv_bfloat16* Bp;
    int bld, n0, nk;
    if (y < 4)      { Bp = d_Wcat_b + (size_t)(y * 128) * 1536;        bld = 1536; n0 = y * 128;             nk = 48; }
    else if (y < 6) { Bp = d_Wihn_b + (size_t)((y - 4) * 128) * 768;   bld = 768;  n0 = 512 + (y - 4) * 128; nk = 24; }
    else            { Bp = d_Whhn_b + (size_t)((y - 6) * 128) * 768;   bld = 768;  n0 = 768 + (y - 6) * 128; nk = 24; }
    const int hoff = (y >= 6) ? 256 : 0;   // G3 uses h-halves of A segments

    const __nv_bfloat16* Ap = d_A + (size_t)m0 * AK;

    // A' column base for chunk c
    auto acol_of = [&](int c) -> int {
        int kg = c * 32;
        if (y < 4) return kg;
        int seg = kg >> 8;
        return seg * 512 + (kg & 255) + hoff;
    };

    // load one stage: A 128x32, B 128x32 (4 cp16 per thread)
    auto load_stage = [&](int c, int s) {
        int acol = acol_of(c);
        int bcol = c * 32;
#pragma unroll
        for (int it = 0; it < 2; it++) {
            int idx = tid + it * 256;          // 0..511
            int row = idx >> 2, cc = idx & 3;
            cp16(smem_u32(&sA[s][row][cc * 8]), Ap + (size_t)row * AK + acol + cc * 8);
            cp16(smem_u32(&sB[s][row][cc * 8]), Bp + (size_t)row * bld + bcol + cc * 8);
        }
        CP_COMMIT();
    };

    float acc[4][4][4];
#pragma unroll
    for (int i = 0; i < 4; i++)
#pragma unroll
        for (int j = 0; j < 4; j++)
#pragma unroll
            for (int v = 0; v < 4; v++) acc[i][j][v] = 0.f;

    load_stage(0, 0);
    if (nk > 1) load_stage(1, 1);

    for (int c = 0; c < nk; c++) {
        const int s = c & 1;
        CP_WAIT1();
        __syncthreads();

#pragma unroll
        for (int ks = 0; ks < 2; ks++) {
            const int k0 = ks * 16;
            // A fragments: 4 m-subtiles via ldmatrix.x4
            uint32_t af[4][4];
#pragma unroll
            for (int ms = 0; ms < 4; ms++) {
                uint32_t addr = smem_u32(&sA[s][wm + ms * 16 + (lane & 15)][k0 + ((lane >> 4) << 3)]);
                asm volatile("ldmatrix.sync.aligned.m8n8.x4.shared.b16 {%0,%1,%2,%3}, [%4];"
                             : "=r"(af[ms][0]), "=r"(af[ms][1]), "=r"(af[ms][2]), "=r"(af[ms][3])
                             : "r"(addr));
            }
            // B fragments: 4 n-subtiles via LDS.32 pairs
            uint32_t bf[4][2];
#pragma unroll
            for (int ns = 0; ns < 4; ns++) {
                const uint32_t* bp = (const uint32_t*)&sB[s][wn + ns * 8 + (lane >> 2)][k0 + ((lane & 3) << 1)];
                bf[ns][0] = bp[0];
                bf[ns][1] = bp[4];   // +8 bf16 = +16B
            }
#pragma unroll
            for (int ms = 0; ms < 4; ms++)
#pragma unroll
                for (int ns = 0; ns < 4; ns++) {
                    asm volatile(
                        "mma.sync.aligned.m16n8k16.row.col.f32.bf16.bf16.f32 "
                        "{%0,%1,%2,%3}, {%4,%5,%6,%7}, {%8,%9}, {%0,%1,%2,%3};"
                        : "+f"(acc[ms][ns][0]), "+f"(acc[ms][ns][1]),
                          "+f"(acc[ms][ns][2]), "+f"(acc[ms][ns][3])
                        : "r"(af[ms][0]), "r"(af[ms][1]), "r"(af[ms][2]), "r"(af[ms][3]),
                          "r"(bf[ns][0]), "r"(bf[ns][1]));
                }
        }
        __syncthreads();
        if (c + 2 < nk) load_stage(c + 2, s);
    }

    // epilogue: acc[ms][ns] -> rows m0+wm+ms*16 + lane/4 (+8), cols n0+wn+ns*8+(lane%4)*2
    const int rq = lane >> 2;        // 0..7
    const int cq = (lane & 3) << 1;  // 0,2,4,6
#pragma unroll
    for (int ms = 0; ms < 4; ms++) {
        int r0 = m0 + wm + ms * 16 + rq;
#pragma unroll
        for (int ns = 0; ns < 4; ns++) {
            int col = n0 + wn + ns * 8 + cq;
            float b0 = d_biasv[col], b1 = d_biasv[col + 1];
            float* g0 = d_g + (size_t)r0 * GCOLS + col;
            float* g1 = d_g + (size_t)(r0 + 8) * GCOLS + col;
            *(float2*)g0 = make_float2(acc[ms][ns][0] + b0, acc[ms][ns][1] + b1);
            *(float2*)g1 = make_float2(acc[ms][ns][2] + b0, acc[ms][ns][3] + b1);
        }
    }
}

// ------------------------- initial x = relu(pose@Wp^T + cproj) ---------------
__global__ __launch_bounds__(256) void x_init(const float* __restrict__ W_in) {
    int b = blockIdx.x, j = threadIdx.x;
    __shared__ float sp[16];
    if (j < POSED) sp[j] = d_pose[b * POSED + j];
    __syncthreads();
    float acc = d_cproj[(size_t)b * HID + j];
#pragma unroll
    for (int k = 0; k < POSED; k++) acc += sp[k] * W_in[(size_t)j * IN_DIM + k];
    float x = fmaxf(acc, 0.f);
    __nv_bfloat16 hi, lo; bf16_split(x, hi, lo);
    size_t base = (size_t)b * AK;
    d_A[base + j] = hi;
    d_A[base + 512 + j] = lo;
    d_A[base + 1024 + j] = hi;
}

// ------------------------- gates + h + pose + quat + next-x ------------------
__global__ __launch_bounds__(256) void gate_kernel(
    const float* __restrict__ W_out, const float* __restrict__ b_out,
    const float* __restrict__ W_in,
    float* __restrict__ out, int t, int T)
{
    int b = blockIdx.x, j = threadIdx.x;
    const float* g = d_g + (size_t)b * GCOLS;

    float sr = g[j], sz = g[256 + j], in_ = g[512 + j], hn = g[768 + j];
    float r = 1.f / (1.f + expf(-sr));
    float z = 1.f / (1.f + expf(-sz));
    float n = tanhf(in_ + r * hn);

    float hprev = d_h[(size_t)b * HID + j];
    float hnew = (1.f - z) * n + z * hprev;
    d_h[(size_t)b * HID + j] = hnew;

    size_t base = (size_t)b * AK;
    {
        __nv_bfloat16 hi, lo; bf16_split(hnew, hi, lo);
        d_A[base + 256 + j] = hi;
        d_A[base + 768 + j] = lo;
        d_A[base + 1280 + j] = hi;
    }

    __shared__ float warp_part[POSED][8];
#pragma unroll
    for (int p = 0; p < POSED; p++) {
        float v = hnew * W_out[p * HID + j];
#pragma unroll
        for (int o = 16; o > 0; o >>= 1)
            v += __shfl_down_sync(0xffffffffu, v, o);
        if ((j & 31) == 0) warp_part[p][j >> 5] = v;
    }
    __syncthreads();

    __shared__ float pnew[16];
    if (j < POSED) {
        float s = 0.f;
#pragma unroll
        for (int w = 0; w < 8; w++) s += warp_part[j][w];
        pnew[j] = d_pose[b * POSED + j] + s + b_out[j];
    }
    __syncthreads();

    __shared__ float spf[16];
    if (j < POSED) {
        float v = pnew[j];
        if (j >= 3 && j <= 6) {
            float q = sqrtf(pnew[3]*pnew[3] + pnew[4]*pnew[4] +
                            pnew[5]*pnew[5] + pnew[6]*pnew[6]);
            v /= fmaxf(q, 1e-12f);
        }
        spf[j] = v;
        d_pose[b * POSED + j] = v;
        out[((size_t)b * T + t) * POSED + j] = v;
    }
    __syncthreads();

    float acc = d_cproj[(size_t)b * HID + j];
#pragma unroll
    for (int k = 0; k < POSED; k++) acc += spf[k] * W_in[(size_t)j * IN_DIM + k];
    float x = fmaxf(acc, 0.f);
    __nv_bfloat16 hi, lo; bf16_split(x, hi, lo);
    d_A[base + j] = hi;
    d_A[base + 512 + j] = lo;
    d_A[base + 1024 + j] = hi;
}

// ------------------------- launch --------------------------------------------
extern "C" void kernel_launch(void* const* d_in, const int* in_sizes, int n_in,
                              void* d_out, int out_size)
{
    const float* last_pose = (const float*)d_in[0];
    const float* context   = (const float*)d_in[1];
    const float* W_in  = (const float*)d_in[3];
    const float* b_in  = (const float*)d_in[4];
    const float* W_ih  = (const float*)d_in[5];
    const float* b_ih  = (const float*)d_in[6];
    const float* W_hh  = (const float*)d_in[7];
    const float* b_hh  = (const float*)d_in[8];
    const float* W_out = (const float*)d_in[9];
    const float* b_out = (const float*)d_in[10];
    float* out = (float*)d_out;

    const int T = out_size / (BATCH * POSED);

    init_kernel<<<(BATCH * HID + 255) / 256, 256>>>(last_pose);
    prep_kernel<<<(512 * 1536 + 255) / 256, 256>>>(W_ih, W_hh, b_ih, b_hh, W_in);
    cproj_gemm<<<dim3(BATCH / 128, 2), 256>>>(context, b_in);
    x_init<<<BATCH, 256>>>(W_in);

    for (int t = 0; t < T; t++) {
        step_gemm_mma<<<dim3(BATCH / 128, 8), 256>>>();
        gate_kernel<<<BATCH, 256>>>(W_out, b_out, W_in, out, t, T);
    }
}